// round 3
// baseline (speedup 1.0000x reference)
#include <cuda_runtime.h>
#include <cuda_bf16.h>
#include <cstdint>

#define NN 100000
#define RR 8
#define EE 800000
#define DD 128
#define BB 4
#define RN (RR*NN)        // 800000
#define RE (RR*EE)        // 6400000
#define SCAN_BLOCKS ((RN + 1023) / 1024)   // 782

// ---------------- device scratch (static, no allocation) ----------------
__device__ int   g_is64;
__device__ int   g_deg[RN];
__device__ int   g_scan[RN];
__device__ int   g_bsum[1024];
__device__ int   g_bsumx[1024];
__device__ int   g_rowstart[RN];
__device__ int   g_cursor[RN];
__device__ float g_invdeg[RN];
__device__ int   g_csr[RE];
__device__ float g_Y[(size_t)NN * 512];   // 204.8 MB
__device__ float g_h1[(size_t)NN * DD];
__device__ float g_h2[(size_t)NN * DD];

// ---------------- edge index helpers ----------------
__device__ __forceinline__ int edge_at(const void* p, int i, int is64) {
    if (is64) return (int)((const long long*)p)[i];
    return ((const int*)p)[i];
}

__global__ void k_detect(const void* srcp, const void* dstp) {
    if (threadIdx.x == 0 && blockIdx.x == 0) {
        const long long* s = (const long long*)srcp;
        const long long* d = (const long long*)dstp;
        int ok = 1;
        for (int i = 0; i < 64; i++) {
            long long a = s[i], b = d[i];
            if (a < 0 || a >= NN || b < 0 || b >= NN) { ok = 0; break; }
        }
        g_is64 = ok;
    }
}

__global__ void k_zero() {
    int i = blockIdx.x * blockDim.x + threadIdx.x;
    if (i < RN) { g_deg[i] = 0; g_cursor[i] = 0; }
}

__global__ void k_degree(const void* dstp) {
    int i = blockIdx.x * blockDim.x + threadIdx.x;
    if (i >= RE) return;
    int is64 = g_is64;
    int d = edge_at(dstp, i, is64);
    int r = i / EE;
    atomicAdd(&g_deg[r * NN + d], 1);
}

__global__ void k_scan1() {
    __shared__ int sh[1024];
    int gid = blockIdx.x * 1024 + threadIdx.x;
    int v = (gid < RN) ? g_deg[gid] : 0;
    sh[threadIdx.x] = v;
    __syncthreads();
    for (int off = 1; off < 1024; off <<= 1) {
        int t = (threadIdx.x >= off) ? sh[threadIdx.x - off] : 0;
        __syncthreads();
        sh[threadIdx.x] += t;
        __syncthreads();
    }
    if (gid < RN) g_scan[gid] = sh[threadIdx.x];
    if (threadIdx.x == 1023) g_bsum[blockIdx.x] = sh[1023];
}

__global__ void k_scan2(int nb) {
    __shared__ int sh[1024];
    int v = (threadIdx.x < nb) ? g_bsum[threadIdx.x] : 0;
    sh[threadIdx.x] = v;
    __syncthreads();
    for (int off = 1; off < 1024; off <<= 1) {
        int t = (threadIdx.x >= off) ? sh[threadIdx.x - off] : 0;
        __syncthreads();
        sh[threadIdx.x] += t;
        __syncthreads();
    }
    if (threadIdx.x < nb) g_bsumx[threadIdx.x] = sh[threadIdx.x] - v;
}

__global__ void k_scan3() {
    int gid = blockIdx.x * blockDim.x + threadIdx.x;
    if (gid >= RN) return;
    int deg = g_deg[gid];
    g_rowstart[gid] = g_scan[gid] - deg + g_bsumx[gid / 1024];
    g_invdeg[gid] = 1.0f / (float)max(deg, 1);
}

__global__ void k_fill(const void* srcp, const void* dstp) {
    int i = blockIdx.x * blockDim.x + threadIdx.x;
    if (i >= RE) return;
    int is64 = g_is64;
    int s = edge_at(srcp, i, is64);
    int d = edge_at(dstp, i, is64);
    int r = i / EE;
    int row = r * NN + d;
    int pos = g_rowstart[row] + atomicAdd(&g_cursor[row], 1);
    g_csr[pos] = s;
}

// One warp per destination node; accumulates all 8 relations, folds the basis
// combination w_comp[r][b] * invdeg on the fly, writes Y[n, 0:512].
__global__ void k_gather(const float* __restrict__ x, const float* __restrict__ wcomp) {
    __shared__ float swc[RR * BB];
    if (threadIdx.x < RR * BB) swc[threadIdx.x] = wcomp[threadIdx.x];
    __syncthreads();
    int warp = threadIdx.x >> 5;
    int lane = threadIdx.x & 31;
    int n = blockIdx.x * 8 + warp;
    if (n >= NN) return;

    float4 acc[BB];
    #pragma unroll
    for (int b = 0; b < BB; b++) acc[b] = make_float4(0.f, 0.f, 0.f, 0.f);

    #pragma unroll
    for (int r = 0; r < RR; r++) {
        int row = r * NN + n;
        int st = g_rowstart[row];
        int len = g_deg[row];
        float t0 = 0.f, t1 = 0.f, t2 = 0.f, t3 = 0.f;
        for (int j = 0; j < len; j++) {
            int s = g_csr[st + j];
            float4 v = *(const float4*)&x[(size_t)s * DD + lane * 4];
            t0 += v.x; t1 += v.y; t2 += v.z; t3 += v.w;
        }
        float iv = g_invdeg[row];
        #pragma unroll
        for (int b = 0; b < BB; b++) {
            float c = swc[r * BB + b] * iv;
            acc[b].x += c * t0; acc[b].y += c * t1;
            acc[b].z += c * t2; acc[b].w += c * t3;
        }
    }
    #pragma unroll
    for (int b = 0; b < BB; b++)
        *(float4*)&g_Y[(size_t)n * 512 + b * DD + lane * 4] = acc[b];
}

// ---------------- tf32 mma.sync GEMM ----------------
// C[M,128] = A[M,K] @ B[K,128]  (+Cin)(+bias)(relu?)
// CTA: 128x128 tile, 256 threads = 8 warps (4 M x 2 N), warp tile 32x64.
// SMEM is fragment-major so fragment fetches are LDS.128 / LDS.64.

__device__ __forceinline__ uint32_t f2tf32(float f) {
    uint32_t r; asm("cvt.rna.tf32.f32 %0, %1;" : "=r"(r) : "f"(f));
    return r;
}

__device__ __forceinline__ void mma_tf32(float* d, const uint4& a, const uint2& b) {
    asm volatile(
        "mma.sync.aligned.m16n8k8.row.col.f32.tf32.tf32.f32 "
        "{%0,%1,%2,%3}, {%4,%5,%6,%7}, {%8,%9}, {%0,%1,%2,%3};"
        : "+f"(d[0]), "+f"(d[1]), "+f"(d[2]), "+f"(d[3])
        : "r"(a.x), "r"(a.y), "r"(a.z), "r"(a.w), "r"(b.x), "r"(b.y));
}

#define BK 32
#define A_STAGE (128 * BK)                  // floats per A stage (16KB)
#define B_STAGE (BK * 128)                  // floats per B stage (16KB)
#define GEMM_SMEM ((2 * A_STAGE + 2 * B_STAGE) * 4)   // 64KB dynamic

// A frag slot: ((kc*8 + mb)*32 + lane)*4 + reg   (kc: k8 chunk, mb: m16 block)
// B frag slot: ((kc*16 + nb)*32 + lane)*2 + reg  (nb: n8 block)

__device__ __forceinline__ void ldg_tileA(const float* __restrict__ A, int K, int M,
                                          int r0, int kt, int t, float4* ra) {
    #pragma unroll
    for (int p = 0; p < 4; p++) {
        int idx = t + 256 * p;
        int row = idx >> 3, c4 = idx & 7;
        int gr = r0 + row;
        float4 v = make_float4(0.f, 0.f, 0.f, 0.f);
        if (gr < M) v = *(const float4*)&A[(size_t)gr * K + kt + c4 * 4];
        ra[p] = v;
    }
}
__device__ __forceinline__ void ldg_tileB(const float* __restrict__ Bm, int kt, int t,
                                          float4* rb) {
    #pragma unroll
    for (int p = 0; p < 4; p++) {
        int idx = t + 256 * p;
        int k = idx >> 5, c4 = idx & 31;
        rb[p] = *(const float4*)&Bm[(size_t)(kt + k) * 128 + c4 * 4];
    }
}
__device__ __forceinline__ void sts_tile(float* sA, float* sB, int t,
                                         const float4* ra, const float4* rb) {
    #pragma unroll
    for (int p = 0; p < 4; p++) {
        int idx = t + 256 * p;
        {   // A scatter
            int row = idx >> 3, c4 = idx & 7;
            int mb = row >> 4, r16 = row & 15;
            int g = r16 & 7, hi = r16 >> 3;
            const float* v = (const float*)&ra[p];
            #pragma unroll
            for (int j = 0; j < 4; j++) {
                int col = c4 * 4 + j;
                int kc = col >> 3, cc = col & 7;
                int tg = cc & 3, ch = cc >> 2;
                int lane = (g << 2) | tg;
                int reg = ch * 2 + hi;
                sA[((kc * 8 + mb) * 32 + lane) * 4 + reg] =
                    __uint_as_float(f2tf32(v[j]));
            }
        }
        {   // B scatter
            int k = idx >> 5, c4 = idx & 31;
            int kc = k >> 3, kk = k & 7;
            int tg = kk & 3, hb = kk >> 2;
            const float* v = (const float*)&rb[p];
            #pragma unroll
            for (int j = 0; j < 4; j++) {
                int n = c4 * 4 + j;
                int nb = n >> 3, g = n & 7;
                int lane = (g << 2) | tg;
                sB[((kc * 16 + nb) * 32 + lane) * 2 + hb] =
                    __uint_as_float(f2tf32(v[j]));
            }
        }
    }
}

__global__ void __launch_bounds__(256, 1)
k_gemm_mma(const float* __restrict__ A, int K, int M,
           const float* __restrict__ Bm,
           const float* __restrict__ Cin, float* __restrict__ Cout,
           const float* __restrict__ bias, int relu) {
    extern __shared__ float smem[];
    float* sA[2] = { smem, smem + A_STAGE };
    float* sB[2] = { smem + 2 * A_STAGE, smem + 2 * A_STAGE + B_STAGE };

    const int t = threadIdx.x;
    const int wid = t >> 5, lane = t & 31;
    const int wm = wid >> 1, wn = wid & 1;         // 4 x 2 warp grid
    const int g = lane >> 2, tg = lane & 3;
    const int r0 = blockIdx.x * 128;

    float acc[2][8][4];
    #pragma unroll
    for (int mi = 0; mi < 2; mi++)
        #pragma unroll
        for (int nj = 0; nj < 8; nj++)
            #pragma unroll
            for (int q = 0; q < 4; q++) acc[mi][nj][q] = 0.f;

    float4 ra[4], rb[4];
    ldg_tileA(A, K, M, r0, 0, t, ra);
    ldg_tileB(Bm, 0, t, rb);
    sts_tile(sA[0], sB[0], t, ra, rb);
    __syncthreads();

    const int nt = K / BK;
    for (int c = 0; c < nt; c++) {
        int cur = c & 1;
        if (c + 1 < nt) {
            ldg_tileA(A, K, M, r0, (c + 1) * BK, t, ra);
            ldg_tileB(Bm, (c + 1) * BK, t, rb);
        }
        float* cA = sA[cur];
        float* cB = sB[cur];
        #pragma unroll
        for (int kc = 0; kc < 4; kc++) {
            uint4 af[2];
            #pragma unroll
            for (int mi = 0; mi < 2; mi++) {
                int mb = wm * 2 + mi;
                af[mi] = *(const uint4*)&cA[((kc * 8 + mb) * 32 + lane) * 4];
            }
            #pragma unroll
            for (int nj = 0; nj < 8; nj++) {
                int nb = wn * 8 + nj;
                uint2 bf = *(const uint2*)&cB[((kc * 16 + nb) * 32 + lane) * 2];
                mma_tf32(acc[0][nj], af[0], bf);
                mma_tf32(acc[1][nj], af[1], bf);
            }
        }
        if (c + 1 < nt) {
            __syncthreads();
            sts_tile(sA[cur ^ 1], sB[cur ^ 1], t, ra, rb);
            __syncthreads();
        }
    }

    // epilogue
    #pragma unroll
    for (int mi = 0; mi < 2; mi++) {
        #pragma unroll
        for (int hi = 0; hi < 2; hi++) {
            int row = r0 + wm * 32 + mi * 16 + hi * 8 + g;
            if (row >= M) continue;
            #pragma unroll
            for (int nj = 0; nj < 8; nj++) {
                int col = wn * 64 + nj * 8 + 2 * tg;
                float v0 = acc[mi][nj][hi * 2 + 0];
                float v1 = acc[mi][nj][hi * 2 + 1];
                if (Cin) {
                    float2 ci = *(const float2*)&Cin[(size_t)row * 128 + col];
                    v0 += ci.x; v1 += ci.y;
                }
                if (bias) {
                    float2 bi = *(const float2*)&bias[col];
                    v0 += bi.x; v1 += bi.y;
                }
                if (relu) { v0 = fmaxf(v0, 0.f); v1 = fmaxf(v1, 0.f); }
                float2 o; o.x = v0; o.y = v1;
                *(float2*)&Cout[(size_t)row * 128 + col] = o;
            }
        }
    }
}

// ---------------- launch ----------------
extern "C" void kernel_launch(void* const* d_in, const int* in_sizes, int n_in,
                              void* d_out, int out_size) {
    const float* x      = (const float*)d_in[0];
    const void*  esrc   = d_in[1];
    const void*  edst   = d_in[2];
    const float* wcomp  = (const float*)d_in[3];
    const float* bases  = (const float*)d_in[4];   // [4,128,128] == flat [512,128]
    const float* loopw  = (const float*)d_in[5];
    const float* hbias  = (const float*)d_in[6];
    const float* ngnn   = (const float*)d_in[7];   // [2,128,128]
    float* out = (float*)d_out;

    float *pY, *pH1, *pH2;
    cudaGetSymbolAddress((void**)&pY,  g_Y);
    cudaGetSymbolAddress((void**)&pH1, g_h1);
    cudaGetSymbolAddress((void**)&pH2, g_h2);

    cudaFuncSetAttribute(k_gemm_mma, cudaFuncAttributeMaxDynamicSharedMemorySize, GEMM_SMEM);

    k_detect<<<1, 32>>>(esrc, edst);
    k_zero<<<(RN + 255) / 256, 256>>>();
    k_degree<<<RE / 256, 256>>>(edst);
    k_scan1<<<SCAN_BLOCKS, 1024>>>();
    k_scan2<<<1, 1024>>>(SCAN_BLOCKS);
    k_scan3<<<(RN + 255) / 256, 256>>>();
    k_fill<<<RE / 256, 256>>>(esrc, edst);
    k_gather<<<(NN + 7) / 8, 256>>>(x, wcomp);

    int gblocks = (NN + 127) / 128;   // 782
    // h1 = Y @ bases_flat (basis-fused relation GEMM, K=512)
    k_gemm_mma<<<gblocks, 256, GEMM_SMEM>>>(pY, 512, NN, bases, nullptr, pH1, nullptr, 0);
    // h1 = relu(h1 + x @ loop_weight + bias)
    k_gemm_mma<<<gblocks, 256, GEMM_SMEM>>>(x, 128, NN, loopw, pH1, pH1, hbias, 1);
    // h2 = relu(h1 @ ngnn_w[0])
    k_gemm_mma<<<gblocks, 256, GEMM_SMEM>>>(pH1, 128, NN, ngnn, nullptr, pH2, nullptr, 1);
    // out = relu(h2 @ ngnn_w[1])
    k_gemm_mma<<<gblocks, 256, GEMM_SMEM>>>(pH2, 128, NN, ngnn + 128 * 128, nullptr, out, nullptr, 1);
}

// round 6
// speedup vs baseline: 1.0209x; 1.0209x over previous
#include <cuda_runtime.h>
#include <cuda_bf16.h>
#include <cstdint>

#define NN 100000
#define RR 8
#define EE 800000
#define DD 128
#define BB 4
#define RN (RR*NN)        // 800000
#define RE (RR*EE)        // 6400000
#define SCAN_BLOCKS ((RN + 1023) / 1024)   // 782

// ---------------- device scratch (static, no allocation) ----------------
__device__ int   g_is64;
__device__ int   g_deg[RN];
__device__ int   g_scan[RN];
__device__ int   g_bsum[1024];
__device__ int   g_bsumx[1024];
__device__ int   g_rowstart[RN];
__device__ int   g_cursor[RN];
__device__ float g_invdeg[RN];
__device__ int   g_csr[RE];
__device__ float g_Y[(size_t)NN * 512];   // 204.8 MB
__device__ float g_h1[(size_t)NN * DD];
__device__ float g_h2[(size_t)NN * DD];

// ---------------- edge index helpers ----------------
__device__ __forceinline__ int edge_at(const void* p, int i, int is64) {
    if (is64) return (int)((const long long*)p)[i];
    return ((const int*)p)[i];
}

__global__ void k_detect(const void* srcp, const void* dstp) {
    if (threadIdx.x == 0 && blockIdx.x == 0) {
        const long long* s = (const long long*)srcp;
        const long long* d = (const long long*)dstp;
        int ok = 1;
        for (int i = 0; i < 64; i++) {
            long long a = s[i], b = d[i];
            if (a < 0 || a >= NN || b < 0 || b >= NN) { ok = 0; break; }
        }
        g_is64 = ok;
    }
}

__global__ void k_zero() {
    int i = blockIdx.x * blockDim.x + threadIdx.x;
    if (i < RN) { g_deg[i] = 0; g_cursor[i] = 0; }
}

__global__ void k_degree(const void* dstp) {
    int i = blockIdx.x * blockDim.x + threadIdx.x;
    if (i >= RE) return;
    int is64 = g_is64;
    int d = edge_at(dstp, i, is64);
    int r = i / EE;
    atomicAdd(&g_deg[r * NN + d], 1);
}

__global__ void k_scan1() {
    __shared__ int sh[1024];
    int gid = blockIdx.x * 1024 + threadIdx.x;
    int v = (gid < RN) ? g_deg[gid] : 0;
    sh[threadIdx.x] = v;
    __syncthreads();
    for (int off = 1; off < 1024; off <<= 1) {
        int t = (threadIdx.x >= off) ? sh[threadIdx.x - off] : 0;
        __syncthreads();
        sh[threadIdx.x] += t;
        __syncthreads();
    }
    if (gid < RN) g_scan[gid] = sh[threadIdx.x];
    if (threadIdx.x == 1023) g_bsum[blockIdx.x] = sh[1023];
}

__global__ void k_scan2(int nb) {
    __shared__ int sh[1024];
    int v = (threadIdx.x < nb) ? g_bsum[threadIdx.x] : 0;
    sh[threadIdx.x] = v;
    __syncthreads();
    for (int off = 1; off < 1024; off <<= 1) {
        int t = (threadIdx.x >= off) ? sh[threadIdx.x - off] : 0;
        __syncthreads();
        sh[threadIdx.x] += t;
        __syncthreads();
    }
    if (threadIdx.x < nb) g_bsumx[threadIdx.x] = sh[threadIdx.x] - v;
}

__global__ void k_scan3() {
    int gid = blockIdx.x * blockDim.x + threadIdx.x;
    if (gid >= RN) return;
    int deg = g_deg[gid];
    g_rowstart[gid] = g_scan[gid] - deg + g_bsumx[gid / 1024];
    g_invdeg[gid] = 1.0f / (float)max(deg, 1);
}

__global__ void k_fill(const void* srcp, const void* dstp) {
    int i = blockIdx.x * blockDim.x + threadIdx.x;
    if (i >= RE) return;
    int is64 = g_is64;
    int s = edge_at(srcp, i, is64);
    int d = edge_at(dstp, i, is64);
    int r = i / EE;
    int row = r * NN + d;
    int pos = g_rowstart[row] + atomicAdd(&g_cursor[row], 1);
    g_csr[pos] = s;
}

// One warp per destination node; accumulates all 8 relations, folds the basis
// combination w_comp[r][b] * invdeg on the fly, writes Y[n, 0:512].
__global__ void k_gather(const float* __restrict__ x, const float* __restrict__ wcomp) {
    __shared__ float swc[RR * BB];
    if (threadIdx.x < RR * BB) swc[threadIdx.x] = wcomp[threadIdx.x];
    __syncthreads();
    int warp = threadIdx.x >> 5;
    int lane = threadIdx.x & 31;
    int n = blockIdx.x * 8 + warp;
    if (n >= NN) return;

    float4 acc[BB];
    #pragma unroll
    for (int b = 0; b < BB; b++) acc[b] = make_float4(0.f, 0.f, 0.f, 0.f);

    #pragma unroll
    for (int r = 0; r < RR; r++) {
        int row = r * NN + n;
        int st = g_rowstart[row];
        int len = g_deg[row];
        float t0 = 0.f, t1 = 0.f, t2 = 0.f, t3 = 0.f;
        for (int j = 0; j < len; j++) {
            int s = g_csr[st + j];
            float4 v = *(const float4*)&x[(size_t)s * DD + lane * 4];
            t0 += v.x; t1 += v.y; t2 += v.z; t3 += v.w;
        }
        float iv = g_invdeg[row];
        #pragma unroll
        for (int b = 0; b < BB; b++) {
            float c = swc[r * BB + b] * iv;
            acc[b].x += c * t0; acc[b].y += c * t1;
            acc[b].z += c * t2; acc[b].w += c * t3;
        }
    }
    #pragma unroll
    for (int b = 0; b < BB; b++)
        *(float4*)&g_Y[(size_t)n * 512 + b * DD + lane * 4] = acc[b];
}

// ---------------- SIMT GEMM: C[M,128] = A[M,K] @ B[K,128] (+Cin)(+bias)(relu?)
// sm_103a pass: packed f32x2 FFMA2 (2x fp32 rate). Plain pass: scalar fallback.
// 128x128 block tile, 256 threads, 8x8 microtile.
//  - fast path rows: ty + 16*i (strided), cols: tx*8 + 2*j + {0,1} (paired)
//  - A staged duplicated ((a,a) f32x2) -> FFMA2 broadcast operand is one LDS.64
//  - B staged as natural column pairs in [16][4][16] f32x2 (conflict-free LDS.64)

#define FMA_F32X2(d, a, b) \
    asm("fma.rn.f32x2 %0, %1, %2, %3;" : "=l"(d) : "l"(a), "l"(b), "l"(d))

__global__ void __launch_bounds__(256, 2)
k_gemm(const float* __restrict__ A, int K, int M,
       const float* __restrict__ Bm,
       const float* __restrict__ Cin, float* __restrict__ Cout,
       const float* __restrict__ bias, int relu) {
#if defined(__CUDA_ARCH_FEAT_SM103_ALL) || defined(__CUDA_ARCH_FEAT_SM100_ALL)
    // ================= f32x2 packed path =================
    __shared__ float2 As2[16][128];      // [k][row] duplicated (a,a)   16KB
    __shared__ float2 Bs2[16][4][16];    // [k][pair j][tx] natural pairs 8KB
    const int t = threadIdx.x;
    const int tx = t & 15, ty = t >> 4;
    const int r0 = blockIdx.x * 128;

    unsigned long long acc[8][4];
    #pragma unroll
    for (int i = 0; i < 8; i++)
        #pragma unroll
        for (int j = 0; j < 4; j++) acc[i][j] = 0ull;

    for (int kt = 0; kt < K; kt += 16) {
        // stage A tile (rows r0..r0+127, cols kt..kt+15), duplicated
        {
            int rowA = t >> 2;
            int colA = (t & 3) * 4;
            #pragma unroll
            for (int p = 0; p < 2; p++) {
                int rr = rowA + p * 64;
                int gr = r0 + rr;
                float4 v = make_float4(0.f, 0.f, 0.f, 0.f);
                if (gr < M) v = *(const float4*)&A[(size_t)gr * K + kt + colA];
                As2[colA + 0][rr] = make_float2(v.x, v.x);
                As2[colA + 1][rr] = make_float2(v.y, v.y);
                As2[colA + 2][rr] = make_float2(v.z, v.z);
                As2[colA + 3][rr] = make_float2(v.w, v.w);
            }
        }
        // stage B tile (rows kt..kt+15, 128 cols) as pairs
        {
            int rowB = t >> 5;
            int colB = (t & 31) * 4;
            int tx2 = colB >> 3;
            int j0 = (colB & 7) >> 1;       // 0 or 2
            #pragma unroll
            for (int p = 0; p < 2; p++) {
                int rb = rowB + p * 8;
                float4 v = *(const float4*)&Bm[(size_t)(kt + rb) * 128 + colB];
                Bs2[rb][j0 + 0][tx2] = make_float2(v.x, v.y);
                Bs2[rb][j0 + 1][tx2] = make_float2(v.z, v.w);
            }
        }
        __syncthreads();
        #pragma unroll
        for (int k = 0; k < 16; k++) {
            unsigned long long a2[8], b2[4];
            #pragma unroll
            for (int i = 0; i < 8; i++)
                a2[i] = *(const unsigned long long*)&As2[k][ty + 16 * i];
            #pragma unroll
            for (int j = 0; j < 4; j++)
                b2[j] = *(const unsigned long long*)&Bs2[k][j][tx];
            #pragma unroll
            for (int i = 0; i < 8; i++)
                #pragma unroll
                for (int j = 0; j < 4; j++)
                    FMA_F32X2(acc[i][j], a2[i], b2[j]);
        }
        __syncthreads();
    }
    // epilogue: rows ty+16i, col pairs tx*8+2j
    #pragma unroll
    for (int i = 0; i < 8; i++) {
        int gr = r0 + ty + 16 * i;
        if (gr >= M) continue;
        #pragma unroll
        for (int j = 0; j < 4; j++) {
            int gc = tx * 8 + 2 * j;
            float v0 = __uint_as_float((unsigned)(acc[i][j] & 0xFFFFFFFFull));
            float v1 = __uint_as_float((unsigned)(acc[i][j] >> 32));
            if (Cin) {
                float2 ci = *(const float2*)&Cin[(size_t)gr * 128 + gc];
                v0 += ci.x; v1 += ci.y;
            }
            if (bias) {
                float2 bi = *(const float2*)&bias[gc];
                v0 += bi.x; v1 += bi.y;
            }
            if (relu) { v0 = fmaxf(v0, 0.f); v1 = fmaxf(v1, 0.f); }
            float2 o; o.x = v0; o.y = v1;
            *(float2*)&Cout[(size_t)gr * 128 + gc] = o;
        }
    }
#else
    // ================= scalar fallback (proven R1 kernel) =================
    __shared__ float As[16][132];
    __shared__ float Bs[16][128];
    int t = threadIdx.x;
    int tx = t & 15, ty = t >> 4;
    int r0 = blockIdx.x * 128;

    float acc[8][8];
    #pragma unroll
    for (int i = 0; i < 8; i++)
        #pragma unroll
        for (int j = 0; j < 8; j++) acc[i][j] = 0.f;

    for (int kt = 0; kt < K; kt += 16) {
        int rowA = t >> 2;
        int colA = (t & 3) * 4;
        #pragma unroll
        for (int p = 0; p < 2; p++) {
            int rr = rowA + p * 64;
            int gr = r0 + rr;
            float4 v = make_float4(0.f, 0.f, 0.f, 0.f);
            if (gr < M) v = *(const float4*)&A[(size_t)gr * K + kt + colA];
            As[colA + 0][rr] = v.x; As[colA + 1][rr] = v.y;
            As[colA + 2][rr] = v.z; As[colA + 3][rr] = v.w;
        }
        int rowB = t >> 5;
        int colB = (t & 31) * 4;
        #pragma unroll
        for (int p = 0; p < 2; p++) {
            int rb = rowB + p * 8;
            float4 v = *(const float4*)&Bm[(size_t)(kt + rb) * 128 + colB];
            *(float4*)&Bs[rb][colB] = v;
        }
        __syncthreads();
        #pragma unroll
        for (int k = 0; k < 16; k++) {
            float a[8], b[8];
            #pragma unroll
            for (int i = 0; i < 8; i++) a[i] = As[k][ty + 16 * i];
            #pragma unroll
            for (int j = 0; j < 8; j++) b[j] = Bs[k][tx + 16 * j];
            #pragma unroll
            for (int i = 0; i < 8; i++)
                #pragma unroll
                for (int j = 0; j < 8; j++) acc[i][j] += a[i] * b[j];
        }
        __syncthreads();
    }
    #pragma unroll
    for (int i = 0; i < 8; i++) {
        int gr = r0 + ty + 16 * i;
        if (gr >= M) continue;
        #pragma unroll
        for (int j = 0; j < 8; j++) {
            int gc = tx + 16 * j;
            float v = acc[i][j];
            if (Cin)  v += Cin[(size_t)gr * 128 + gc];
            if (bias) v += bias[gc];
            if (relu) v = fmaxf(v, 0.f);
            Cout[(size_t)gr * 128 + gc] = v;
        }
    }
#endif
}

// ---------------- launch ----------------
extern "C" void kernel_launch(void* const* d_in, const int* in_sizes, int n_in,
                              void* d_out, int out_size) {
    const float* x      = (const float*)d_in[0];
    const void*  esrc   = d_in[1];
    const void*  edst   = d_in[2];
    const float* wcomp  = (const float*)d_in[3];
    const float* bases  = (const float*)d_in[4];   // [4,128,128] == flat [512,128]
    const float* loopw  = (const float*)d_in[5];
    const float* hbias  = (const float*)d_in[6];
    const float* ngnn   = (const float*)d_in[7];   // [2,128,128]
    float* out = (float*)d_out;

    float *pY, *pH1, *pH2;
    cudaGetSymbolAddress((void**)&pY,  g_Y);
    cudaGetSymbolAddress((void**)&pH1, g_h1);
    cudaGetSymbolAddress((void**)&pH2, g_h2);

    k_detect<<<1, 32>>>(esrc, edst);
    k_zero<<<(RN + 255) / 256, 256>>>();
    k_degree<<<RE / 256, 256>>>(edst);
    k_scan1<<<SCAN_BLOCKS, 1024>>>();
    k_scan2<<<1, 1024>>>(SCAN_BLOCKS);
    k_scan3<<<(RN + 255) / 256, 256>>>();
    k_fill<<<RE / 256, 256>>>(esrc, edst);
    k_gather<<<(NN + 7) / 8, 256>>>(x, wcomp);

    int gblocks = (NN + 127) / 128;   // 782
    // h1 = Y @ bases_flat (basis-fused relation GEMM, K=512)
    k_gemm<<<gblocks, 256>>>(pY, 512, NN, bases, nullptr, pH1, nullptr, 0);
    // h1 = relu(h1 + x @ loop_weight + bias)
    k_gemm<<<gblocks, 256>>>(x, 128, NN, loopw, pH1, pH1, hbias, 1);
    // h2 = relu(h1 @ ngnn_w[0])
    k_gemm<<<gblocks, 256>>>(pH1, 128, NN, ngnn, nullptr, pH2, nullptr, 1);
    // out = relu(h2 @ ngnn_w[1])
    k_gemm<<<gblocks, 256>>>(pH2, 128, NN, ngnn + 128 * 128, nullptr, out, nullptr, 1);
}

// round 8
// speedup vs baseline: 1.1229x; 1.1000x over previous
#include <cuda_runtime.h>
#include <cuda_bf16.h>
#include <cstdint>

#define NN 100000
#define RR 8
#define EE 800000
#define DD 128
#define BB 4
#define RN (RR*NN)        // 800000
#define RE (RR*EE)        // 6400000
#define SCAN_BLOCKS ((RN + 1023) / 1024)   // 782

// ---------------- device scratch (static, no allocation) ----------------
__device__ int   g_is64;
__device__ int   g_deg[RN];
__device__ int   g_scan[RN];
__device__ int   g_bsum[1024];
__device__ int   g_bsumx[1024];
__device__ int   g_rowstart[RN];
__device__ int   g_cursor[RN];
__device__ float g_invdeg[RN];
__device__ int   g_csr[RE];
__device__ float g_Y[(size_t)NN * 512];   // 204.8 MB
__device__ float g_h1[(size_t)NN * DD];
__device__ float g_h2[(size_t)NN * DD];

// ---------------- edge index helpers ----------------
__device__ __forceinline__ int edge_at(const void* p, int i, int is64) {
    if (is64) return (int)((const long long*)p)[i];
    return ((const int*)p)[i];
}

__global__ void k_detect(const void* srcp, const void* dstp) {
    if (threadIdx.x == 0 && blockIdx.x == 0) {
        const long long* s = (const long long*)srcp;
        const long long* d = (const long long*)dstp;
        int ok = 1;
        for (int i = 0; i < 64; i++) {
            long long a = s[i], b = d[i];
            if (a < 0 || a >= NN || b < 0 || b >= NN) { ok = 0; break; }
        }
        g_is64 = ok;
    }
}

__global__ void k_zero() {
    int i = blockIdx.x * blockDim.x + threadIdx.x;
    if (i < RN) { g_deg[i] = 0; g_cursor[i] = 0; }
}

__global__ void k_degree(const void* dstp) {
    int i = blockIdx.x * blockDim.x + threadIdx.x;
    if (i >= RE) return;
    int is64 = g_is64;
    int d = edge_at(dstp, i, is64);
    int r = i / EE;
    atomicAdd(&g_deg[r * NN + d], 1);
}

__global__ void k_scan1() {
    __shared__ int sh[1024];
    int gid = blockIdx.x * 1024 + threadIdx.x;
    int v = (gid < RN) ? g_deg[gid] : 0;
    sh[threadIdx.x] = v;
    __syncthreads();
    for (int off = 1; off < 1024; off <<= 1) {
        int t = (threadIdx.x >= off) ? sh[threadIdx.x - off] : 0;
        __syncthreads();
        sh[threadIdx.x] += t;
        __syncthreads();
    }
    if (gid < RN) g_scan[gid] = sh[threadIdx.x];
    if (threadIdx.x == 1023) g_bsum[blockIdx.x] = sh[1023];
}

__global__ void k_scan2(int nb) {
    __shared__ int sh[1024];
    int v = (threadIdx.x < nb) ? g_bsum[threadIdx.x] : 0;
    sh[threadIdx.x] = v;
    __syncthreads();
    for (int off = 1; off < 1024; off <<= 1) {
        int t = (threadIdx.x >= off) ? sh[threadIdx.x - off] : 0;
        __syncthreads();
        sh[threadIdx.x] += t;
        __syncthreads();
    }
    if (threadIdx.x < nb) g_bsumx[threadIdx.x] = sh[threadIdx.x] - v;
}

__global__ void k_scan3() {
    int gid = blockIdx.x * blockDim.x + threadIdx.x;
    if (gid >= RN) return;
    int deg = g_deg[gid];
    g_rowstart[gid] = g_scan[gid] - deg + g_bsumx[gid / 1024];
    g_invdeg[gid] = 1.0f / (float)max(deg, 1);
}

__global__ void k_fill(const void* srcp, const void* dstp) {
    int i = blockIdx.x * blockDim.x + threadIdx.x;
    if (i >= RE) return;
    int is64 = g_is64;
    int s = edge_at(srcp, i, is64);
    int d = edge_at(dstp, i, is64);
    int r = i / EE;
    int row = r * NN + d;
    int pos = g_rowstart[row] + atomicAdd(&g_cursor[row], 1);
    g_csr[pos] = s;
}

// One warp per destination node; accumulates all 8 relations, folds the basis
// combination w_comp[r][b] * invdeg on the fly, writes Y[n, 0:512].
__global__ void k_gather(const float* __restrict__ x, const float* __restrict__ wcomp) {
    __shared__ float swc[RR * BB];
    if (threadIdx.x < RR * BB) swc[threadIdx.x] = wcomp[threadIdx.x];
    __syncthreads();
    int warp = threadIdx.x >> 5;
    int lane = threadIdx.x & 31;
    int n = blockIdx.x * 8 + warp;
    if (n >= NN) return;

    float4 acc[BB];
    #pragma unroll
    for (int b = 0; b < BB; b++) acc[b] = make_float4(0.f, 0.f, 0.f, 0.f);

    #pragma unroll
    for (int r = 0; r < RR; r++) {
        int row = r * NN + n;
        int st = g_rowstart[row];
        int len = g_deg[row];
        float t0 = 0.f, t1 = 0.f, t2 = 0.f, t3 = 0.f;
        if (len > 0) {
            int s = g_csr[st];
            for (int j = 0; j < len - 1; j++) {
                int sn = g_csr[st + j + 1];           // prefetch next index
                float4 v = *(const float4*)&x[(size_t)s * DD + lane * 4];
                t0 += v.x; t1 += v.y; t2 += v.z; t3 += v.w;
                s = sn;
            }
            float4 v = *(const float4*)&x[(size_t)s * DD + lane * 4];
            t0 += v.x; t1 += v.y; t2 += v.z; t3 += v.w;
        }
        float iv = g_invdeg[row];
        #pragma unroll
        for (int b = 0; b < BB; b++) {
            float c = swc[r * BB + b] * iv;
            acc[b].x += c * t0; acc[b].y += c * t1;
            acc[b].z += c * t2; acc[b].w += c * t3;
        }
    }
    #pragma unroll
    for (int b = 0; b < BB; b++)
        *(float4*)&g_Y[(size_t)n * 512 + b * DD + lane * 4] = acc[b];
}

// ---------------- SIMT fp32 GEMM, vectorized microtiles ----------------
// C[M,128] = A1[M,K1] @ B1[K1,128] (+ A2[M,K2] @ B2[K2,128]) (+bias)(relu?)
// 128x128 tile, 256 threads, contiguous 8x8 microtile: rows ty*8+i, cols tx*8+j.
// Inner loop per k: 2 LDS.128 (A, broadcast) + 2 LDS.128 (B) + 64 FFMA.
__global__ void __launch_bounds__(256, 2)
k_gemm(const float* __restrict__ A1, int K1, const float* __restrict__ B1,
       const float* __restrict__ A2, int K2, const float* __restrict__ B2,
       int M, float* __restrict__ Cout,
       const float* __restrict__ bias, int relu) {
    __shared__ float As[16][132];   // [k][row], padded (writes scatter by k)
    __shared__ float Bs[16][128];   // [k][col]
    const int t = threadIdx.x;
    const int tx = t & 15, ty = t >> 4;
    const int r0 = blockIdx.x * 128;

    float acc[8][8];
    #pragma unroll
    for (int i = 0; i < 8; i++)
        #pragma unroll
        for (int j = 0; j < 8; j++) acc[i][j] = 0.f;

    #pragma unroll
    for (int ph = 0; ph < 2; ph++) {
        const float* A = (ph == 0) ? A1 : A2;
        const float* Bm = (ph == 0) ? B1 : B2;
        const int K = (ph == 0) ? K1 : K2;
        if (A == nullptr) continue;

        for (int kt = 0; kt < K; kt += 16) {
            // stage A tile transposed: As[k][row]
            {
                int rowA = t >> 2;
                int colA = (t & 3) * 4;
                #pragma unroll
                for (int p = 0; p < 2; p++) {
                    int rr = rowA + p * 64;
                    int gr = r0 + rr;
                    float4 v = make_float4(0.f, 0.f, 0.f, 0.f);
                    if (gr < M) v = *(const float4*)&A[(size_t)gr * K + kt + colA];
                    As[colA + 0][rr] = v.x; As[colA + 1][rr] = v.y;
                    As[colA + 2][rr] = v.z; As[colA + 3][rr] = v.w;
                }
            }
            // stage B tile: Bs[k][col]
            {
                int rowB = t >> 5;
                int colB = (t & 31) * 4;
                #pragma unroll
                for (int p = 0; p < 2; p++) {
                    int rb = rowB + p * 8;
                    float4 v = *(const float4*)&Bm[(size_t)(kt + rb) * 128 + colB];
                    *(float4*)&Bs[rb][colB] = v;
                }
            }
            __syncthreads();
            #pragma unroll
            for (int k = 0; k < 16; k++) {
                float4 a0 = *(const float4*)&As[k][ty * 8];
                float4 a1 = *(const float4*)&As[k][ty * 8 + 4];
                float4 b0 = *(const float4*)&Bs[k][tx * 8];
                float4 b1 = *(const float4*)&Bs[k][tx * 8 + 4];
                float a[8] = { a0.x, a0.y, a0.z, a0.w, a1.x, a1.y, a1.z, a1.w };
                float b[8] = { b0.x, b0.y, b0.z, b0.w, b1.x, b1.y, b1.z, b1.w };
                #pragma unroll
                for (int i = 0; i < 8; i++)
                    #pragma unroll
                    for (int j = 0; j < 8; j++) acc[i][j] += a[i] * b[j];
            }
            __syncthreads();
        }
    }

    // epilogue: contiguous float4 stores
    float4 bia0 = make_float4(0.f, 0.f, 0.f, 0.f), bia1 = bia0;
    if (bias) {
        bia0 = *(const float4*)&bias[tx * 8];
        bia1 = *(const float4*)&bias[tx * 8 + 4];
    }
    #pragma unroll
    for (int i = 0; i < 8; i++) {
        int gr = r0 + ty * 8 + i;
        if (gr >= M) continue;
        float4 v0 = make_float4(acc[i][0], acc[i][1], acc[i][2], acc[i][3]);
        float4 v1 = make_float4(acc[i][4], acc[i][5], acc[i][6], acc[i][7]);
        v0.x += bia0.x; v0.y += bia0.y; v0.z += bia0.z; v0.w += bia0.w;
        v1.x += bia1.x; v1.y += bia1.y; v1.z += bia1.z; v1.w += bia1.w;
        if (relu) {
            v0.x = fmaxf(v0.x, 0.f); v0.y = fmaxf(v0.y, 0.f);
            v0.z = fmaxf(v0.z, 0.f); v0.w = fmaxf(v0.w, 0.f);
            v1.x = fmaxf(v1.x, 0.f); v1.y = fmaxf(v1.y, 0.f);
            v1.z = fmaxf(v1.z, 0.f); v1.w = fmaxf(v1.w, 0.f);
        }
        *(float4*)&Cout[(size_t)gr * 128 + tx * 8]     = v0;
        *(float4*)&Cout[(size_t)gr * 128 + tx * 8 + 4] = v1;
    }
}

// ---------------- launch ----------------
extern "C" void kernel_launch(void* const* d_in, const int* in_sizes, int n_in,
                              void* d_out, int out_size) {
    const float* x      = (const float*)d_in[0];
    const void*  esrc   = d_in[1];
    const void*  edst   = d_in[2];
    const float* wcomp  = (const float*)d_in[3];
    const float* bases  = (const float*)d_in[4];   // [4,128,128] == flat [512,128]
    const float* loopw  = (const float*)d_in[5];
    const float* hbias  = (const float*)d_in[6];
    const float* ngnn   = (const float*)d_in[7];   // [2,128,128]
    float* out = (float*)d_out;

    float *pY, *pH1, *pH2;
    cudaGetSymbolAddress((void**)&pY,  g_Y);
    cudaGetSymbolAddress((void**)&pH1, g_h1);
    cudaGetSymbolAddress((void**)&pH2, g_h2);

    k_detect<<<1, 32>>>(esrc, edst);
    k_zero<<<(RN + 255) / 256, 256>>>();
    k_degree<<<RE / 256, 256>>>(edst);
    k_scan1<<<SCAN_BLOCKS, 1024>>>();
    k_scan2<<<1, 1024>>>(SCAN_BLOCKS);
    k_scan3<<<(RN + 255) / 256, 256>>>();
    k_fill<<<RE / 256, 256>>>(esrc, edst);
    k_gather<<<(NN + 7) / 8, 256>>>(x, wcomp);

    int gblocks = (NN + 127) / 128;   // 782
    // h1 = relu(Y @ bases_flat + x @ loop_weight + bias)   [fused GEMM1+2]
    k_gemm<<<gblocks, 256>>>(pY, 512, bases, x, 128, loopw, NN, pH1, hbias, 1);
    // h2 = relu(h1 @ ngnn_w[0])
    k_gemm<<<gblocks, 256>>>(pH1, 128, ngnn, nullptr, 0, nullptr, NN, pH2, nullptr, 1);
    // out = relu(h2 @ ngnn_w[1])
    k_gemm<<<gblocks, 256>>>(pH2, 128, ngnn + 128 * 128, nullptr, 0, nullptr, NN, out, nullptr, 1);
}

// round 9
// speedup vs baseline: 1.5743x; 1.4019x over previous
#include <cuda_runtime.h>
#include <cuda_bf16.h>
#include <cstdint>

#define NN 100000
#define RR 8
#define EE 800000
#define DD 128
#define BB 4
#define RN (RR*NN)        // 800000
#define RE (RR*EE)        // 6400000
#define SCAN_BLOCKS ((RN + 1023) / 1024)   // 782

// ---------------- device scratch (static, no allocation) ----------------
__device__ int   g_is64;
__device__ int   g_deg[RN];
__device__ int   g_scan[RN];
__device__ int   g_bsum[1024];
__device__ int   g_bsumx[1024];
__device__ int   g_rowstart[RN];
__device__ int   g_cursor[RN];
__device__ float g_invdeg[RN];
__device__ int   g_csr[RE];
__device__ float g_Y[(size_t)NN * 512];   // 204.8 MB
__device__ float g_h1[(size_t)NN * DD];
__device__ float g_h2[(size_t)NN * DD];

// ---------------- edge index helpers ----------------
__device__ __forceinline__ int edge_at(const void* p, int i, int is64) {
    if (is64) return (int)((const long long*)p)[i];
    return ((const int*)p)[i];
}

__global__ void k_detect(const void* srcp, const void* dstp) {
    if (threadIdx.x == 0 && blockIdx.x == 0) {
        const long long* s = (const long long*)srcp;
        const long long* d = (const long long*)dstp;
        int ok = 1;
        for (int i = 0; i < 64; i++) {
            long long a = s[i], b = d[i];
            if (a < 0 || a >= NN || b < 0 || b >= NN) { ok = 0; break; }
        }
        g_is64 = ok;
    }
}

__global__ void k_zero() {
    int i = blockIdx.x * blockDim.x + threadIdx.x;
    if (i < RN) { g_deg[i] = 0; g_cursor[i] = 0; }
}

__global__ void k_degree(const void* dstp) {
    int i = blockIdx.x * blockDim.x + threadIdx.x;
    if (i >= RE) return;
    int is64 = g_is64;
    int d = edge_at(dstp, i, is64);
    int r = i / EE;
    atomicAdd(&g_deg[r * NN + d], 1);
}

__global__ void k_scan1() {
    __shared__ int sh[1024];
    int gid = blockIdx.x * 1024 + threadIdx.x;
    int v = (gid < RN) ? g_deg[gid] : 0;
    sh[threadIdx.x] = v;
    __syncthreads();
    for (int off = 1; off < 1024; off <<= 1) {
        int t = (threadIdx.x >= off) ? sh[threadIdx.x - off] : 0;
        __syncthreads();
        sh[threadIdx.x] += t;
        __syncthreads();
    }
    if (gid < RN) g_scan[gid] = sh[threadIdx.x];
    if (threadIdx.x == 1023) g_bsum[blockIdx.x] = sh[1023];
}

__global__ void k_scan2(int nb) {
    __shared__ int sh[1024];
    int v = (threadIdx.x < nb) ? g_bsum[threadIdx.x] : 0;
    sh[threadIdx.x] = v;
    __syncthreads();
    for (int off = 1; off < 1024; off <<= 1) {
        int t = (threadIdx.x >= off) ? sh[threadIdx.x - off] : 0;
        __syncthreads();
        sh[threadIdx.x] += t;
        __syncthreads();
    }
    if (threadIdx.x < nb) g_bsumx[threadIdx.x] = sh[threadIdx.x] - v;
}

__global__ void k_scan3() {
    int gid = blockIdx.x * blockDim.x + threadIdx.x;
    if (gid >= RN) return;
    int deg = g_deg[gid];
    g_rowstart[gid] = g_scan[gid] - deg + g_bsumx[gid / 1024];
    g_invdeg[gid] = 1.0f / (float)max(deg, 1);
}

__global__ void k_fill(const void* srcp, const void* dstp) {
    int i = blockIdx.x * blockDim.x + threadIdx.x;
    if (i >= RE) return;
    int is64 = g_is64;
    int s = edge_at(srcp, i, is64);
    int d = edge_at(dstp, i, is64);
    int r = i / EE;
    int row = r * NN + d;
    int pos = g_rowstart[row] + atomicAdd(&g_cursor[row], 1);
    g_csr[pos] = s;
}

// One warp per destination node; accumulates all 8 relations, folds the basis
// combination w_comp[r][b] * invdeg on the fly, writes Y[n, 0:512].
__global__ void k_gather(const float* __restrict__ x, const float* __restrict__ wcomp) {
    __shared__ float swc[RR * BB];
    if (threadIdx.x < RR * BB) swc[threadIdx.x] = wcomp[threadIdx.x];
    __syncthreads();
    int warp = threadIdx.x >> 5;
    int lane = threadIdx.x & 31;
    int n = blockIdx.x * 8 + warp;
    if (n >= NN) return;

    float4 acc[BB];
    #pragma unroll
    for (int b = 0; b < BB; b++) acc[b] = make_float4(0.f, 0.f, 0.f, 0.f);

    #pragma unroll
    for (int r = 0; r < RR; r++) {
        int row = r * NN + n;
        int st = g_rowstart[row];
        int len = g_deg[row];
        float t0 = 0.f, t1 = 0.f, t2 = 0.f, t3 = 0.f;
        if (len > 0) {
            int s = g_csr[st];
            for (int j = 0; j < len - 1; j++) {
                int sn = g_csr[st + j + 1];
                float4 v = *(const float4*)&x[(size_t)s * DD + lane * 4];
                t0 += v.x; t1 += v.y; t2 += v.z; t3 += v.w;
                s = sn;
            }
            float4 v = *(const float4*)&x[(size_t)s * DD + lane * 4];
            t0 += v.x; t1 += v.y; t2 += v.z; t3 += v.w;
        }
        float iv = g_invdeg[row];
        #pragma unroll
        for (int b = 0; b < BB; b++) {
            float c = swc[r * BB + b] * iv;
            acc[b].x += c * t0; acc[b].y += c * t1;
            acc[b].z += c * t2; acc[b].w += c * t3;
        }
    }
    #pragma unroll
    for (int b = 0; b < BB; b++)
        *(float4*)&g_Y[(size_t)n * 512 + b * DD + lane * 4] = acc[b];
}

// ---------------- tf32 mma.sync GEMM, canonical-layout SMEM ----------------
// C[M,128] = A1[M,K1]@B1 (+ A2[M,K2]@B2) (+bias)(relu?)
// CTA tile 128x128, 8 warps in 4(M) x 2(N): warp tile 32x64. BK=32.
// SMEM: As[32][136] = A^T (k-major, pad 136 -> row stride == 8 mod 32:
//       fragment loads are 32-lane bank permutations, conflict-free).
//       Bs[32][136] natural [k][n], staged with STS.128.
__device__ __forceinline__ uint32_t f2tf32(float f) {
    uint32_t r; asm("cvt.rna.tf32.f32 %0, %1;" : "=r"(r) : "f"(f));
    return r;
}
__device__ __forceinline__ void mma_tf32(float* d, const uint32_t* a, uint32_t b0, uint32_t b1) {
    asm volatile(
        "mma.sync.aligned.m16n8k8.row.col.f32.tf32.tf32.f32 "
        "{%0,%1,%2,%3}, {%4,%5,%6,%7}, {%8,%9}, {%0,%1,%2,%3};"
        : "+f"(d[0]), "+f"(d[1]), "+f"(d[2]), "+f"(d[3])
        : "r"(a[0]), "r"(a[1]), "r"(a[2]), "r"(a[3]), "r"(b0), "r"(b1));
}

#define APAD 136
__global__ void __launch_bounds__(256, 2)
k_gemm(const float* __restrict__ A1, int K1, const float* __restrict__ B1,
       const float* __restrict__ A2, int K2, const float* __restrict__ B2,
       int M, float* __restrict__ Cout,
       const float* __restrict__ bias, int relu) {
    __shared__ uint32_t As[32][APAD];
    __shared__ uint32_t Bs[32][APAD];
    const int t = threadIdx.x;
    const int lane = t & 31, wid = t >> 5;
    const int g = lane >> 2, tg = lane & 3;
    const int wm = wid >> 1, wn = wid & 1;      // 4 x 2 warp grid
    const int r0 = blockIdx.x * 128;

    float acc[2][8][4];
    #pragma unroll
    for (int mi = 0; mi < 2; mi++)
        #pragma unroll
        for (int nj = 0; nj < 8; nj++)
            #pragma unroll
            for (int q = 0; q < 4; q++) acc[mi][nj][q] = 0.f;

    float4 ra[4], rb[4];

    // register-load tile kt of (A,B)
    #define LDG_TILE(A, Bm, K, kt) do { \
        _Pragma("unroll") \
        for (int p = 0; p < 4; p++) { \
            int idx = t + 256 * p; \
            int rowA = idx >> 3, c4 = idx & 7; \
            int gr = r0 + rowA; \
            float4 v = make_float4(0.f, 0.f, 0.f, 0.f); \
            if (gr < M) v = *(const float4*)&(A)[(size_t)gr * (K) + (kt) + c4 * 4]; \
            ra[p] = v; \
            int rbw = idx >> 5, cB = (idx & 31) * 4; \
            rb[p] = *(const float4*)&(Bm)[(size_t)((kt) + rbw) * 128 + cB]; \
        } \
    } while(0)
    // SMEM-store the register tile (tf32-rounded)
    #define STS_TILE() do { \
        _Pragma("unroll") \
        for (int p = 0; p < 4; p++) { \
            int idx = t + 256 * p; \
            int rowA = idx >> 3, c4 = idx & 7; \
            As[c4 * 4 + 0][rowA] = f2tf32(ra[p].x); \
            As[c4 * 4 + 1][rowA] = f2tf32(ra[p].y); \
            As[c4 * 4 + 2][rowA] = f2tf32(ra[p].z); \
            As[c4 * 4 + 3][rowA] = f2tf32(ra[p].w); \
            int rbw = idx >> 5, cB = (idx & 31) * 4; \
            uint4 ub; \
            ub.x = f2tf32(rb[p].x); ub.y = f2tf32(rb[p].y); \
            ub.z = f2tf32(rb[p].z); ub.w = f2tf32(rb[p].w); \
            *(uint4*)&Bs[rbw][cB] = ub; \
        } \
    } while(0)

    const float* Aph[2] = { A1, A2 };
    const float* Bph[2] = { B1, B2 };
    const int    Kph[2] = { K1, K2 };

    // preload first tile
    LDG_TILE(A1, B1, K1, 0);

    #pragma unroll
    for (int ph = 0; ph < 2; ph++) {
        const float* A = Aph[ph];
        const float* Bm = Bph[ph];
        const int K = Kph[ph];
        if (A == nullptr) continue;
        const int nt = K >> 5;
        for (int c = 0; c < nt; c++) {
            STS_TILE();
            __syncthreads();
            // prefetch next tile (this phase or next phase) into regs
            if (c + 1 < nt) {
                LDG_TILE(A, Bm, K, (c + 1) * 32);
            } else if (ph == 0 && Aph[1] != nullptr) {
                LDG_TILE(Aph[1], Bph[1], Kph[1], 0);
            }
            // MMA over the staged tile
            #pragma unroll
            for (int kc = 0; kc < 4; kc++) {
                int kb = kc * 8;
                uint32_t af[2][4];
                #pragma unroll
                for (int mi = 0; mi < 2; mi++) {
                    int m = wm * 32 + mi * 16 + g;
                    af[mi][0] = As[kb + tg][m];
                    af[mi][1] = As[kb + tg][m + 8];
                    af[mi][2] = As[kb + tg + 4][m];
                    af[mi][3] = As[kb + tg + 4][m + 8];
                }
                #pragma unroll
                for (int nj = 0; nj < 8; nj++) {
                    int n = wn * 64 + nj * 8 + g;
                    uint32_t b0 = Bs[kb + tg][n];
                    uint32_t b1 = Bs[kb + tg + 4][n];
                    mma_tf32(acc[0][nj], af[0], b0, b1);
                    mma_tf32(acc[1][nj], af[1], b0, b1);
                }
            }
            __syncthreads();
        }
    }

    // epilogue: thread (g,tg) owns rows m0+g(+8), cols n0+nj*8+2tg(+1)
    #pragma unroll
    for (int mi = 0; mi < 2; mi++) {
        #pragma unroll
        for (int hi = 0; hi < 2; hi++) {
            int row = r0 + wm * 32 + mi * 16 + hi * 8 + g;
            if (row >= M) continue;
            #pragma unroll
            for (int nj = 0; nj < 8; nj++) {
                int col = wn * 64 + nj * 8 + 2 * tg;
                float v0 = acc[mi][nj][hi * 2 + 0];
                float v1 = acc[mi][nj][hi * 2 + 1];
                if (bias) {
                    float2 bi = *(const float2*)&bias[col];
                    v0 += bi.x; v1 += bi.y;
                }
                if (relu) { v0 = fmaxf(v0, 0.f); v1 = fmaxf(v1, 0.f); }
                float2 o; o.x = v0; o.y = v1;
                *(float2*)&Cout[(size_t)row * 128 + col] = o;
            }
        }
    }
    #undef LDG_TILE
    #undef STS_TILE
}

// ---------------- launch ----------------
extern "C" void kernel_launch(void* const* d_in, const int* in_sizes, int n_in,
                              void* d_out, int out_size) {
    const float* x      = (const float*)d_in[0];
    const void*  esrc   = d_in[1];
    const void*  edst   = d_in[2];
    const float* wcomp  = (const float*)d_in[3];
    const float* bases  = (const float*)d_in[4];   // [4,128,128] == flat [512,128]
    const float* loopw  = (const float*)d_in[5];
    const float* hbias  = (const float*)d_in[6];
    const float* ngnn   = (const float*)d_in[7];   // [2,128,128]
    float* out = (float*)d_out;

    float *pY, *pH1, *pH2;
    cudaGetSymbolAddress((void**)&pY,  g_Y);
    cudaGetSymbolAddress((void**)&pH1, g_h1);
    cudaGetSymbolAddress((void**)&pH2, g_h2);

    k_detect<<<1, 32>>>(esrc, edst);
    k_zero<<<(RN + 255) / 256, 256>>>();
    k_degree<<<RE / 256, 256>>>(edst);
    k_scan1<<<SCAN_BLOCKS, 1024>>>();
    k_scan2<<<1, 1024>>>(SCAN_BLOCKS);
    k_scan3<<<(RN + 255) / 256, 256>>>();
    k_fill<<<RE / 256, 256>>>(esrc, edst);
    k_gather<<<(NN + 7) / 8, 256>>>(x, wcomp);

    int gblocks = (NN + 127) / 128;   // 782
    // h1 = relu(Y @ bases_flat + x @ loop_weight + bias)   [fused]
    k_gemm<<<gblocks, 256>>>(pY, 512, bases, x, 128, loopw, NN, pH1, hbias, 1);
    // h2 = relu(h1 @ ngnn_w[0])
    k_gemm<<<gblocks, 256>>>(pH1, 128, ngnn, nullptr, 0, nullptr, NN, pH2, nullptr, 1);
    // out = relu(h2 @ ngnn_w[1])
    k_gemm<<<gblocks, 256>>>(pH2, 128, ngnn + 128 * 128, nullptr, 0, nullptr, NN, out, nullptr, 1);
}

// round 10
// speedup vs baseline: 1.7188x; 1.0918x over previous
#include <cuda_runtime.h>
#include <cuda_bf16.h>
#include <cuda_fp16.h>
#include <cstdint>

#define NN 100000
#define RR 8
#define EE 800000
#define DD 128
#define BB 4
#define RN (RR*NN)        // 800000
#define RE (RR*EE)        // 6400000
#define SCAN_BLOCKS ((RN + 1023) / 1024)   // 782

// ---------------- device scratch (static, no allocation) ----------------
__device__ int    g_is64;
__device__ int    g_deg[RN];
__device__ int    g_scan[RN];
__device__ int    g_bsum[1024];
__device__ int    g_bsumx[1024];
__device__ int    g_rowstart[RN];
__device__ int    g_cursor[RN];
__device__ float  g_invdeg[RN];
__device__ int    g_csr[RE];
__device__ __half g_xh[(size_t)NN * DD];   // packed fp16 copy of x (25.6 MB)
__device__ float  g_Y[(size_t)NN * 512];   // 204.8 MB
__device__ float  g_h1[(size_t)NN * DD];
__device__ float  g_h2[(size_t)NN * DD];

// ---------------- edge index helpers ----------------
// int64 edge values are < 2^31, little-endian: low 32-bit word == value.
__device__ __forceinline__ int edge_at(const void* p, int i, int is64) {
    if (is64) return ((const int*)p)[2 * i];
    return ((const int*)p)[i];
}

__global__ void k_detect(const void* srcp, const void* dstp) {
    if (threadIdx.x == 0 && blockIdx.x == 0) {
        const long long* s = (const long long*)srcp;
        const long long* d = (const long long*)dstp;
        int ok = 1;
        for (int i = 0; i < 64; i++) {
            long long a = s[i], b = d[i];
            if (a < 0 || a >= NN || b < 0 || b >= NN) { ok = 0; break; }
        }
        g_is64 = ok;
    }
}

__global__ void k_zero() {
    int i = blockIdx.x * blockDim.x + threadIdx.x;
    if (i < RN) { g_deg[i] = 0; g_cursor[i] = 0; }
}

// pack x to fp16
__global__ void k_x2h(const float* __restrict__ x) {
    int i = blockIdx.x * blockDim.x + threadIdx.x;   // one float4 -> half4
    if (i >= NN * DD / 4) return;
    float4 v = *(const float4*)&x[(size_t)i * 4];
    __half2 h0 = __floats2half2_rn(v.x, v.y);
    __half2 h1 = __floats2half2_rn(v.z, v.w);
    uint2 o;
    o.x = *(uint32_t*)&h0;
    o.y = *(uint32_t*)&h1;
    *(uint2*)&g_xh[(size_t)i * 4] = o;
}

__global__ void k_degree(const void* dstp) {
    int i = blockIdx.x * blockDim.x + threadIdx.x;
    if (i >= RE) return;
    int is64 = g_is64;
    int d = edge_at(dstp, i, is64);
    int r = i / EE;
    atomicAdd(&g_deg[r * NN + d], 1);
}

__global__ void k_scan1() {
    __shared__ int sh[1024];
    int gid = blockIdx.x * 1024 + threadIdx.x;
    int v = (gid < RN) ? g_deg[gid] : 0;
    sh[threadIdx.x] = v;
    __syncthreads();
    for (int off = 1; off < 1024; off <<= 1) {
        int t = (threadIdx.x >= off) ? sh[threadIdx.x - off] : 0;
        __syncthreads();
        sh[threadIdx.x] += t;
        __syncthreads();
    }
    if (gid < RN) g_scan[gid] = sh[threadIdx.x];
    if (threadIdx.x == 1023) g_bsum[blockIdx.x] = sh[1023];
}

__global__ void k_scan2(int nb) {
    __shared__ int sh[1024];
    int v = (threadIdx.x < nb) ? g_bsum[threadIdx.x] : 0;
    sh[threadIdx.x] = v;
    __syncthreads();
    for (int off = 1; off < 1024; off <<= 1) {
        int t = (threadIdx.x >= off) ? sh[threadIdx.x - off] : 0;
        __syncthreads();
        sh[threadIdx.x] += t;
        __syncthreads();
    }
    if (threadIdx.x < nb) g_bsumx[threadIdx.x] = sh[threadIdx.x] - v;
}

__global__ void k_scan3() {
    int gid = blockIdx.x * blockDim.x + threadIdx.x;
    if (gid >= RN) return;
    int deg = g_deg[gid];
    g_rowstart[gid] = g_scan[gid] - deg + g_bsumx[gid / 1024];
    g_invdeg[gid] = 1.0f / (float)max(deg, 1);
}

__global__ void k_fill(const void* srcp, const void* dstp) {
    int i = blockIdx.x * blockDim.x + threadIdx.x;
    if (i >= RE) return;
    int is64 = g_is64;
    int s = edge_at(srcp, i, is64);
    int d = edge_at(dstp, i, is64);
    int r = i / EE;
    int row = r * NN + d;
    int pos = g_rowstart[row] + atomicAdd(&g_cursor[row], 1);
    g_csr[pos] = s;
}

// One warp per destination node; gathers fp16 x rows (half the L2 traffic),
// accumulates fp32, folds w_comp[r][b] * invdeg, writes Y[n, 0:512] fp32.
__global__ void k_gather(const float* __restrict__ wcomp) {
    __shared__ float swc[RR * BB];
    if (threadIdx.x < RR * BB) swc[threadIdx.x] = wcomp[threadIdx.x];
    __syncthreads();
    int warp = threadIdx.x >> 5;
    int lane = threadIdx.x & 31;
    int n = blockIdx.x * 8 + warp;
    if (n >= NN) return;

    float4 acc[BB];
    #pragma unroll
    for (int b = 0; b < BB; b++) acc[b] = make_float4(0.f, 0.f, 0.f, 0.f);

    #pragma unroll
    for (int r = 0; r < RR; r++) {
        int row = r * NN + n;
        int st = g_rowstart[row];
        int len = g_deg[row];
        float t0 = 0.f, t1 = 0.f, t2 = 0.f, t3 = 0.f;
        if (len > 0) {
            int s = g_csr[st];
            for (int j = 0; j < len - 1; j++) {
                int sn = g_csr[st + j + 1];          // prefetch next index
                uint2 hv = *(const uint2*)&g_xh[(size_t)s * DD + lane * 4];
                float2 f0 = __half22float2(*(__half2*)&hv.x);
                float2 f1 = __half22float2(*(__half2*)&hv.y);
                t0 += f0.x; t1 += f0.y; t2 += f1.x; t3 += f1.y;
                s = sn;
            }
            uint2 hv = *(const uint2*)&g_xh[(size_t)s * DD + lane * 4];
            float2 f0 = __half22float2(*(__half2*)&hv.x);
            float2 f1 = __half22float2(*(__half2*)&hv.y);
            t0 += f0.x; t1 += f0.y; t2 += f1.x; t3 += f1.y;
        }
        float iv = g_invdeg[row];
        #pragma unroll
        for (int b = 0; b < BB; b++) {
            float c = swc[r * BB + b] * iv;
            acc[b].x += c * t0; acc[b].y += c * t1;
            acc[b].z += c * t2; acc[b].w += c * t3;
        }
    }
    #pragma unroll
    for (int b = 0; b < BB; b++)
        *(float4*)&g_Y[(size_t)n * 512 + b * DD + lane * 4] = acc[b];
}

// ---------------- tf32 mma.sync GEMM (byte-identical to R9) ----------------
__device__ __forceinline__ uint32_t f2tf32(float f) {
    uint32_t r; asm("cvt.rna.tf32.f32 %0, %1;" : "=r"(r) : "f"(f));
    return r;
}
__device__ __forceinline__ void mma_tf32(float* d, const uint32_t* a, uint32_t b0, uint32_t b1) {
    asm volatile(
        "mma.sync.aligned.m16n8k8.row.col.f32.tf32.tf32.f32 "
        "{%0,%1,%2,%3}, {%4,%5,%6,%7}, {%8,%9}, {%0,%1,%2,%3};"
        : "+f"(d[0]), "+f"(d[1]), "+f"(d[2]), "+f"(d[3])
        : "r"(a[0]), "r"(a[1]), "r"(a[2]), "r"(a[3]), "r"(b0), "r"(b1));
}

#define APAD 136
__global__ void __launch_bounds__(256, 2)
k_gemm(const float* __restrict__ A1, int K1, const float* __restrict__ B1,
       const float* __restrict__ A2, int K2, const float* __restrict__ B2,
       int M, float* __restrict__ Cout,
       const float* __restrict__ bias, int relu) {
    __shared__ uint32_t As[32][APAD];
    __shared__ uint32_t Bs[32][APAD];
    const int t = threadIdx.x;
    const int lane = t & 31, wid = t >> 5;
    const int g = lane >> 2, tg = lane & 3;
    const int wm = wid >> 1, wn = wid & 1;      // 4 x 2 warp grid
    const int r0 = blockIdx.x * 128;

    float acc[2][8][4];
    #pragma unroll
    for (int mi = 0; mi < 2; mi++)
        #pragma unroll
        for (int nj = 0; nj < 8; nj++)
            #pragma unroll
            for (int q = 0; q < 4; q++) acc[mi][nj][q] = 0.f;

    float4 ra[4], rb[4];

    #define LDG_TILE(A, Bm, K, kt) do { \
        _Pragma("unroll") \
        for (int p = 0; p < 4; p++) { \
            int idx = t + 256 * p; \
            int rowA = idx >> 3, c4 = idx & 7; \
            int gr = r0 + rowA; \
            float4 v = make_float4(0.f, 0.f, 0.f, 0.f); \
            if (gr < M) v = *(const float4*)&(A)[(size_t)gr * (K) + (kt) + c4 * 4]; \
            ra[p] = v; \
            int rbw = idx >> 5, cB = (idx & 31) * 4; \
            rb[p] = *(const float4*)&(Bm)[(size_t)((kt) + rbw) * 128 + cB]; \
        } \
    } while(0)
    #define STS_TILE() do { \
        _Pragma("unroll") \
        for (int p = 0; p < 4; p++) { \
            int idx = t + 256 * p; \
            int rowA = idx >> 3, c4 = idx & 7; \
            As[c4 * 4 + 0][rowA] = f2tf32(ra[p].x); \
            As[c4 * 4 + 1][rowA] = f2tf32(ra[p].y); \
            As[c4 * 4 + 2][rowA] = f2tf32(ra[p].z); \
            As[c4 * 4 + 3][rowA] = f2tf32(ra[p].w); \
            int rbw = idx >> 5, cB = (idx & 31) * 4; \
            uint4 ub; \
            ub.x = f2tf32(rb[p].x); ub.y = f2tf32(rb[p].y); \
            ub.z = f2tf32(rb[p].z); ub.w = f2tf32(rb[p].w); \
            *(uint4*)&Bs[rbw][cB] = ub; \
        } \
    } while(0)

    const float* Aph[2] = { A1, A2 };
    const float* Bph[2] = { B1, B2 };
    const int    Kph[2] = { K1, K2 };

    LDG_TILE(A1, B1, K1, 0);

    #pragma unroll
    for (int ph = 0; ph < 2; ph++) {
        const float* A = Aph[ph];
        const float* Bm = Bph[ph];
        const int K = Kph[ph];
        if (A == nullptr) continue;
        const int nt = K >> 5;
        for (int c = 0; c < nt; c++) {
            STS_TILE();
            __syncthreads();
            if (c + 1 < nt) {
                LDG_TILE(A, Bm, K, (c + 1) * 32);
            } else if (ph == 0 && Aph[1] != nullptr) {
                LDG_TILE(Aph[1], Bph[1], Kph[1], 0);
            }
            #pragma unroll
            for (int kc = 0; kc < 4; kc++) {
                int kb = kc * 8;
                uint32_t af[2][4];
                #pragma unroll
                for (int mi = 0; mi < 2; mi++) {
                    int m = wm * 32 + mi * 16 + g;
                    af[mi][0] = As[kb + tg][m];
                    af[mi][1] = As[kb + tg][m + 8];
                    af[mi][2] = As[kb + tg + 4][m];
                    af[mi][3] = As[kb + tg + 4][m + 8];
                }
                #pragma unroll
                for (int nj = 0; nj < 8; nj++) {
                    int n = wn * 64 + nj * 8 + g;
                    uint32_t b0 = Bs[kb + tg][n];
                    uint32_t b1 = Bs[kb + tg + 4][n];
                    mma_tf32(acc[0][nj], af[0], b0, b1);
                    mma_tf32(acc[1][nj], af[1], b0, b1);
                }
            }
            __syncthreads();
        }
    }

    #pragma unroll
    for (int mi = 0; mi < 2; mi++) {
        #pragma unroll
        for (int hi = 0; hi < 2; hi++) {
            int row = r0 + wm * 32 + mi * 16 + hi * 8 + g;
            if (row >= M) continue;
            #pragma unroll
            for (int nj = 0; nj < 8; nj++) {
                int col = wn * 64 + nj * 8 + 2 * tg;
                float v0 = acc[mi][nj][hi * 2 + 0];
                float v1 = acc[mi][nj][hi * 2 + 1];
                if (bias) {
                    float2 bi = *(const float2*)&bias[col];
                    v0 += bi.x; v1 += bi.y;
                }
                if (relu) { v0 = fmaxf(v0, 0.f); v1 = fmaxf(v1, 0.f); }
                float2 o; o.x = v0; o.y = v1;
                *(float2*)&Cout[(size_t)row * 128 + col] = o;
            }
        }
    }
    #undef LDG_TILE
    #undef STS_TILE
}

// ---------------- launch ----------------
extern "C" void kernel_launch(void* const* d_in, const int* in_sizes, int n_in,
                              void* d_out, int out_size) {
    const float* x      = (const float*)d_in[0];
    const void*  esrc   = d_in[1];
    const void*  edst   = d_in[2];
    const float* wcomp  = (const float*)d_in[3];
    const float* bases  = (const float*)d_in[4];   // [4,128,128] == flat [512,128]
    const float* loopw  = (const float*)d_in[5];
    const float* hbias  = (const float*)d_in[6];
    const float* ngnn   = (const float*)d_in[7];   // [2,128,128]
    float* out = (float*)d_out;

    float *pY, *pH1, *pH2;
    cudaGetSymbolAddress((void**)&pY,  g_Y);
    cudaGetSymbolAddress((void**)&pH1, g_h1);
    cudaGetSymbolAddress((void**)&pH2, g_h2);

    k_detect<<<1, 32>>>(esrc, edst);
    k_zero<<<(RN + 255) / 256, 256>>>();
    k_x2h<<<(NN * DD / 4 + 255) / 256, 256>>>(x);
    k_degree<<<RE / 256, 256>>>(edst);
    k_scan1<<<SCAN_BLOCKS, 1024>>>();
    k_scan2<<<1, 1024>>>(SCAN_BLOCKS);
    k_scan3<<<(RN + 255) / 256, 256>>>();
    k_fill<<<RE / 256, 256>>>(esrc, edst);
    k_gather<<<(NN + 7) / 8, 256>>>(wcomp);

    int gblocks = (NN + 127) / 128;   // 782
    // h1 = relu(Y @ bases_flat + x @ loop_weight + bias)   [fused; x fp32]
    k_gemm<<<gblocks, 256>>>(pY, 512, bases, x, 128, loopw, NN, pH1, hbias, 1);
    // h2 = relu(h1 @ ngnn_w[0])
    k_gemm<<<gblocks, 256>>>(pH1, 128, ngnn, nullptr, 0, nullptr, NN, pH2, nullptr, 1);
    // out = relu(h2 @ ngnn_w[1])
    k_gemm<<<gblocks, 256>>>(pH2, 128, ngnn + 128 * 128, nullptr, 0, nullptr, NN, out, nullptr, 1);
}

// round 11
// speedup vs baseline: 2.1598x; 1.2566x over previous
#include <cuda_runtime.h>
#include <cuda_bf16.h>
#include <cuda_fp16.h>
#include <cstdint>

#define NN 100000
#define RR 8
#define EE 800000
#define DD 128
#define BB 4
#define RN (RR*NN)        // 800000
#define RE (RR*EE)        // 6400000
#define SCAN_BLOCKS ((RN + 1023) / 1024)   // 782

// ---------------- device scratch (static, no allocation) ----------------
__device__ int    g_is64;
__device__ int    g_deg[RN];
__device__ int    g_scan[RN];
__device__ int    g_bsum[1024];
__device__ int    g_bsumx[1024];
__device__ int    g_rowstart[RN];
__device__ int    g_cursor[RN];
__device__ float  g_invdeg[RN];
__device__ int    g_csr[RE];
__device__ __half g_xh[(size_t)NN * DD];   // packed fp16 copy of x (25.6 MB)
__device__ float  g_Y[(size_t)NN * 512];   // 204.8 MB
__device__ float  g_h1[(size_t)NN * DD];
__device__ float  g_h2[(size_t)NN * DD];

// ---------------- edge index helpers ----------------
// int64 edge values are < 2^31, little-endian: low 32-bit word == value.
__device__ __forceinline__ int edge_at(const void* p, int i, int is64) {
    if (is64) return ((const int*)p)[2 * i];
    return ((const int*)p)[i];
}

__global__ void k_detect(const void* srcp, const void* dstp) {
    if (threadIdx.x == 0 && blockIdx.x == 0) {
        const long long* s = (const long long*)srcp;
        const long long* d = (const long long*)dstp;
        int ok = 1;
        for (int i = 0; i < 64; i++) {
            long long a = s[i], b = d[i];
            if (a < 0 || a >= NN || b < 0 || b >= NN) { ok = 0; break; }
        }
        g_is64 = ok;
    }
}

__global__ void k_zero() {
    int i = blockIdx.x * blockDim.x + threadIdx.x;
    if (i < RN) { g_deg[i] = 0; g_cursor[i] = 0; }
}

// pack x to fp16
__global__ void k_x2h(const float* __restrict__ x) {
    int i = blockIdx.x * blockDim.x + threadIdx.x;   // one float4 -> half4
    if (i >= NN * DD / 4) return;
    float4 v = *(const float4*)&x[(size_t)i * 4];
    __half2 h0 = __floats2half2_rn(v.x, v.y);
    __half2 h1 = __floats2half2_rn(v.z, v.w);
    uint2 o;
    o.x = *(uint32_t*)&h0;
    o.y = *(uint32_t*)&h1;
    *(uint2*)&g_xh[(size_t)i * 4] = o;
}

__global__ void k_degree(const void* dstp) {
    int i = blockIdx.x * blockDim.x + threadIdx.x;
    if (i >= RE) return;
    int is64 = g_is64;
    int d = edge_at(dstp, i, is64);
    int r = i / EE;
    atomicAdd(&g_deg[r * NN + d], 1);
}

__global__ void k_scan1() {
    __shared__ int sh[1024];
    int gid = blockIdx.x * 1024 + threadIdx.x;
    int v = (gid < RN) ? g_deg[gid] : 0;
    sh[threadIdx.x] = v;
    __syncthreads();
    for (int off = 1; off < 1024; off <<= 1) {
        int t = (threadIdx.x >= off) ? sh[threadIdx.x - off] : 0;
        __syncthreads();
        sh[threadIdx.x] += t;
        __syncthreads();
    }
    if (gid < RN) g_scan[gid] = sh[threadIdx.x];
    if (threadIdx.x == 1023) g_bsum[blockIdx.x] = sh[1023];
}

__global__ void k_scan2(int nb) {
    __shared__ int sh[1024];
    int v = (threadIdx.x < nb) ? g_bsum[threadIdx.x] : 0;
    sh[threadIdx.x] = v;
    __syncthreads();
    for (int off = 1; off < 1024; off <<= 1) {
        int t = (threadIdx.x >= off) ? sh[threadIdx.x - off] : 0;
        __syncthreads();
        sh[threadIdx.x] += t;
        __syncthreads();
    }
    if (threadIdx.x < nb) g_bsumx[threadIdx.x] = sh[threadIdx.x] - v;
}

__global__ void k_scan3() {
    int gid = blockIdx.x * blockDim.x + threadIdx.x;
    if (gid >= RN) return;
    int deg = g_deg[gid];
    g_rowstart[gid] = g_scan[gid] - deg + g_bsumx[gid / 1024];
    g_invdeg[gid] = 1.0f / (float)max(deg, 1);
}

__global__ void k_fill(const void* srcp, const void* dstp) {
    int i = blockIdx.x * blockDim.x + threadIdx.x;
    if (i >= RE) return;
    int is64 = g_is64;
    int s = edge_at(srcp, i, is64);
    int d = edge_at(dstp, i, is64);
    int r = i / EE;
    int row = r * NN + d;
    int pos = g_rowstart[row] + atomicAdd(&g_cursor[row], 1);
    g_csr[pos] = s;
}

// One warp per destination node; gathers fp16 x rows, accumulates fp32,
// folds w_comp[r][b] * invdeg, writes Y[n, 0:512] fp32.
__global__ void k_gather(const float* __restrict__ wcomp) {
    __shared__ float swc[RR * BB];
    if (threadIdx.x < RR * BB) swc[threadIdx.x] = wcomp[threadIdx.x];
    __syncthreads();
    int warp = threadIdx.x >> 5;
    int lane = threadIdx.x & 31;
    int n = blockIdx.x * 8 + warp;
    if (n >= NN) return;

    float4 acc[BB];
    #pragma unroll
    for (int b = 0; b < BB; b++) acc[b] = make_float4(0.f, 0.f, 0.f, 0.f);

    #pragma unroll
    for (int r = 0; r < RR; r++) {
        int row = r * NN + n;
        int st = g_rowstart[row];
        int len = g_deg[row];
        float t0 = 0.f, t1 = 0.f, t2 = 0.f, t3 = 0.f;
        if (len > 0) {
            int s = g_csr[st];
            for (int j = 0; j < len - 1; j++) {
                int sn = g_csr[st + j + 1];
                uint2 hv = *(const uint2*)&g_xh[(size_t)s * DD + lane * 4];
                float2 f0 = __half22float2(*(__half2*)&hv.x);
                float2 f1 = __half22float2(*(__half2*)&hv.y);
                t0 += f0.x; t1 += f0.y; t2 += f1.x; t3 += f1.y;
                s = sn;
            }
            uint2 hv = *(const uint2*)&g_xh[(size_t)s * DD + lane * 4];
            float2 f0 = __half22float2(*(__half2*)&hv.x);
            float2 f1 = __half22float2(*(__half2*)&hv.y);
            t0 += f0.x; t1 += f0.y; t2 += f1.x; t3 += f1.y;
        }
        float iv = g_invdeg[row];
        #pragma unroll
        for (int b = 0; b < BB; b++) {
            float c = swc[r * BB + b] * iv;
            acc[b].x += c * t0; acc[b].y += c * t1;
            acc[b].z += c * t2; acc[b].w += c * t3;
        }
    }
    #pragma unroll
    for (int b = 0; b < BB; b++)
        *(float4*)&g_Y[(size_t)n * 512 + b * DD + lane * 4] = acc[b];
}

// ---------------- fp16 m16n8k16 mma.sync GEMM ----------------
// C[M,128] = A1[M,K1]@B1 (+ A2[M,K2]@B2) (+bias)(relu?)   fp32 accum.
// CTA tile 128x128, 8 warps 4(M)x2(N), warp tile 32x64, BK=32.
// As2[128][20]  : row-major A, half2-packed along k (pad 20 -> conflict-free)
// Bs2[16][132]  : k-pair-packed B, [kp][n] = (B[2kp][n], B[2kp+1][n])
__device__ __forceinline__ uint32_t pack_h2(float a, float b) {
    __half2 h = __floats2half2_rn(a, b);
    return *(uint32_t*)&h;
}
__device__ __forceinline__ void mma_f16(float* d, const uint32_t* a, uint32_t b0, uint32_t b1) {
    asm volatile(
        "mma.sync.aligned.m16n8k16.row.col.f32.f16.f16.f32 "
        "{%0,%1,%2,%3}, {%4,%5,%6,%7}, {%8,%9}, {%0,%1,%2,%3};"
        : "+f"(d[0]), "+f"(d[1]), "+f"(d[2]), "+f"(d[3])
        : "r"(a[0]), "r"(a[1]), "r"(a[2]), "r"(a[3]), "r"(b0), "r"(b1));
}

#define ASTRIDE 20
#define BSTRIDE 132
__global__ void __launch_bounds__(256, 2)
k_gemm(const float* __restrict__ A1, int K1, const float* __restrict__ B1,
       const float* __restrict__ A2, int K2, const float* __restrict__ B2,
       int M, float* __restrict__ Cout,
       const float* __restrict__ bias, int relu) {
    __shared__ uint32_t As2[128][ASTRIDE];   // half2: [row][kp], kp = k/2 (16 valid)
    __shared__ uint32_t Bs2[16][BSTRIDE];    // half2: [kp][n]
    const int t = threadIdx.x;
    const int lane = t & 31, wid = t >> 5;
    const int g = lane >> 2, tg = lane & 3;
    const int wm = wid >> 1, wn = wid & 1;      // 4 x 2 warp grid
    const int r0 = blockIdx.x * 128;

    float acc[2][8][4];
    #pragma unroll
    for (int mi = 0; mi < 2; mi++)
        #pragma unroll
        for (int nj = 0; nj < 8; nj++)
            #pragma unroll
            for (int q = 0; q < 4; q++) acc[mi][nj][q] = 0.f;

    float4 ra[4], rb[4];

    // A: 1024 float4 tasks (idx>>3 = row, idx&7 = k-quad). B: 512 tasks
    // (u>>5 = kp, (u&31)*4 = col), loading global rows 2kp and 2kp+1.
    #define LDG_TILE(A, Bm, K, kt) do { \
        _Pragma("unroll") \
        for (int p = 0; p < 4; p++) { \
            int idx = t + 256 * p; \
            int rowA = idx >> 3, c4 = idx & 7; \
            int gr = r0 + rowA; \
            float4 v = make_float4(0.f, 0.f, 0.f, 0.f); \
            if (gr < M) v = *(const float4*)&(A)[(size_t)gr * (K) + (kt) + c4 * 4]; \
            ra[p] = v; \
        } \
        _Pragma("unroll") \
        for (int p = 0; p < 2; p++) { \
            int u = t + 256 * p; \
            int kp = u >> 5, cB = (u & 31) * 4; \
            rb[2 * p]     = *(const float4*)&(Bm)[(size_t)((kt) + 2 * kp)     * 128 + cB]; \
            rb[2 * p + 1] = *(const float4*)&(Bm)[(size_t)((kt) + 2 * kp + 1) * 128 + cB]; \
        } \
    } while(0)
    #define STS_TILE() do { \
        _Pragma("unroll") \
        for (int p = 0; p < 4; p++) { \
            int idx = t + 256 * p; \
            int rowA = idx >> 3, c4 = idx & 7; \
            As2[rowA][c4 * 2 + 0] = pack_h2(ra[p].x, ra[p].y); \
            As2[rowA][c4 * 2 + 1] = pack_h2(ra[p].z, ra[p].w); \
        } \
        _Pragma("unroll") \
        for (int p = 0; p < 2; p++) { \
            int u = t + 256 * p; \
            int kp = u >> 5, cB = (u & 31) * 4; \
            float4 lo = rb[2 * p], hi = rb[2 * p + 1]; \
            Bs2[kp][cB + 0] = pack_h2(lo.x, hi.x); \
            Bs2[kp][cB + 1] = pack_h2(lo.y, hi.y); \
            Bs2[kp][cB + 2] = pack_h2(lo.z, hi.z); \
            Bs2[kp][cB + 3] = pack_h2(lo.w, hi.w); \
        } \
    } while(0)

    const float* Aph[2] = { A1, A2 };
    const float* Bph[2] = { B1, B2 };
    const int    Kph[2] = { K1, K2 };

    LDG_TILE(A1, B1, K1, 0);

    #pragma unroll
    for (int ph = 0; ph < 2; ph++) {
        const float* A = Aph[ph];
        const float* Bm = Bph[ph];
        const int K = Kph[ph];
        if (A == nullptr) continue;
        const int nt = K >> 5;
        for (int c = 0; c < nt; c++) {
            STS_TILE();
            __syncthreads();
            if (c + 1 < nt) {
                LDG_TILE(A, Bm, K, (c + 1) * 32);
            } else if (ph == 0 && Aph[1] != nullptr) {
                LDG_TILE(Aph[1], Bph[1], Kph[1], 0);
            }
            // two k16 blocks per 32-K tile
            #pragma unroll
            for (int kc = 0; kc < 2; kc++) {
                int kb = kc * 8;                 // half2 base within tile
                uint32_t af[2][4];
                #pragma unroll
                for (int mi = 0; mi < 2; mi++) {
                    int m = wm * 32 + mi * 16 + g;
                    af[mi][0] = As2[m][kb + tg];
                    af[mi][1] = As2[m + 8][kb + tg];
                    af[mi][2] = As2[m][kb + tg + 4];
                    af[mi][3] = As2[m + 8][kb + tg + 4];
                }
                #pragma unroll
                for (int nj = 0; nj < 8; nj++) {
                    int n = wn * 64 + nj * 8 + g;
                    uint32_t b0 = Bs2[kb + tg][n];
                    uint32_t b1 = Bs2[kb + tg + 4][n];
                    mma_f16(acc[0][nj], af[0], b0, b1);
                    mma_f16(acc[1][nj], af[1], b0, b1);
                }
            }
            __syncthreads();
        }
    }

    // epilogue: thread (g,tg) owns rows m0+g(+8), cols n0+nj*8+2tg(+1)
    #pragma unroll
    for (int mi = 0; mi < 2; mi++) {
        #pragma unroll
        for (int hi = 0; hi < 2; hi++) {
            int row = r0 + wm * 32 + mi * 16 + hi * 8 + g;
            if (row >= M) continue;
            #pragma unroll
            for (int nj = 0; nj < 8; nj++) {
                int col = wn * 64 + nj * 8 + 2 * tg;
                float v0 = acc[mi][nj][hi * 2 + 0];
                float v1 = acc[mi][nj][hi * 2 + 1];
                if (bias) {
                    float2 bi = *(const float2*)&bias[col];
                    v0 += bi.x; v1 += bi.y;
                }
                if (relu) { v0 = fmaxf(v0, 0.f); v1 = fmaxf(v1, 0.f); }
                float2 o; o.x = v0; o.y = v1;
                *(float2*)&Cout[(size_t)row * 128 + col] = o;
            }
        }
    }
    #undef LDG_TILE
    #undef STS_TILE
}

// ---------------- launch ----------------
extern "C" void kernel_launch(void* const* d_in, const int* in_sizes, int n_in,
                              void* d_out, int out_size) {
    const float* x      = (const float*)d_in[0];
    const void*  esrc   = d_in[1];
    const void*  edst   = d_in[2];
    const float* wcomp  = (const float*)d_in[3];
    const float* bases  = (const float*)d_in[4];   // [4,128,128] == flat [512,128]
    const float* loopw  = (const float*)d_in[5];
    const float* hbias  = (const float*)d_in[6];
    const float* ngnn   = (const float*)d_in[7];   // [2,128,128]
    float* out = (float*)d_out;

    float *pY, *pH1, *pH2;
    cudaGetSymbolAddress((void**)&pY,  g_Y);
    cudaGetSymbolAddress((void**)&pH1, g_h1);
    cudaGetSymbolAddress((void**)&pH2, g_h2);

    k_detect<<<1, 32>>>(esrc, edst);
    k_zero<<<(RN + 255) / 256, 256>>>();
    k_x2h<<<(NN * DD / 4 + 255) / 256, 256>>>(x);
    k_degree<<<RE / 256, 256>>>(edst);
    k_scan1<<<SCAN_BLOCKS, 1024>>>();
    k_scan2<<<1, 1024>>>(SCAN_BLOCKS);
    k_scan3<<<(RN + 255) / 256, 256>>>();
    k_fill<<<RE / 256, 256>>>(esrc, edst);
    k_gather<<<(NN + 7) / 8, 256>>>(wcomp);

    int gblocks = (NN + 127) / 128;   // 782
    // h1 = relu(Y @ bases_flat + x @ loop_weight + bias)   [fused]
    k_gemm<<<gblocks, 256>>>(pY, 512, bases, x, 128, loopw, NN, pH1, hbias, 1);
    // h2 = relu(h1 @ ngnn_w[0])
    k_gemm<<<gblocks, 256>>>(pH1, 128, ngnn, nullptr, 0, nullptr, NN, pH2, nullptr, 1);
    // out = relu(h2 @ ngnn_w[1])
    k_gemm<<<gblocks, 256>>>(pH2, 128, ngnn + 128 * 128, nullptr, 0, nullptr, NN, out, nullptr, 1);
}